// round 8
// baseline (speedup 1.0000x reference)
#include <cuda_runtime.h>

#define BATCH 256
#define FEAT  512
#define NB    32           // blocks (barrier participants)
#define NT    1024         // threads/block; 8 rows/block, 128 threads/row
#define ROWS_PER_BLK 8

// Scratch + barrier state (allocation-free rule: __device__ globals).
// g_release is a monotone epoch -> replay-safe with no reset node.
__device__ __align__(16) float g_part[NB];   // per-block partial dist sums
__device__ float    g_total;                 // grand total (written by last arriver)
__device__ unsigned g_arrive = 0;
__device__ volatile unsigned g_release = 0;

__global__ void __launch_bounds__(NT) cl_fused_kernel(
    const float* __restrict__ feats,
    const float* __restrict__ centers,
    const int*   __restrict__ labels,
    float*       __restrict__ out)
{
    const int t    = threadIdx.x;
    const int warp = t >> 5;            // 0..31
    const int lane = t & 31;
    const int rg   = warp >> 2;         // row within block: 0..7 (4 warps/row)
    const int b    = blockIdx.x * ROWS_PER_BLK + rg;
    const int l    = t & 127;           // thread within the 128-thread row

    // Early label fetch (start of the dependent gather chain ASAP)
    const long long lab = __ldg(&labels[b]);

    const float4* f4 = reinterpret_cast<const float4*>(feats) + (size_t)b * (FEAT / 4);
    const float4* c4 = reinterpret_cast<const float4*>(centers) + lab * (FEAT / 4);

    float4 f = f4[l];
    float4 c = c4[l];

    float d0 = f.x - c.x, d1 = f.y - c.y, d2 = f.z - c.z, d3 = f.w - c.w;
    float dist = d0 * d0 + d1 * d1 + d2 * d2 + d3 * d3;
    float mx   = fmaxf(fmaxf(f.x, f.y), fmaxf(f.z, f.w));

    // ---- warp reduce dist & max (fixed xor trees, no BAR) ----
    #pragma unroll
    for (int o = 16; o > 0; o >>= 1) {
        dist += __shfl_xor_sync(0xffffffffu, dist, o);
        mx    = fmaxf(mx, __shfl_xor_sync(0xffffffffu, mx, o));
    }

    __shared__ float s_d[32], s_mx[32], s_e[32], s_total;
    if (lane == 0) { s_d[warp] = dist; s_mx[warp] = mx; }
    __syncthreads();   // BAR #1

    // ---- warp 0: block partial via shuffle tree, publish + arrive NOW ----
    unsigned e0 = 0;
    const bool is_t0 = (t == 0);
    if (warp == 0) {
        float v = s_d[lane];
        #pragma unroll
        for (int o = 16; o > 0; o >>= 1)
            v += __shfl_xor_sync(0xffffffffu, v, o);
        if (lane == 0) {
            g_part[blockIdx.x] = v;
            __threadfence();                          // partial visible before arrive
            e0 = g_release;                           // sample epoch pre-arrival
            unsigned my = atomicAdd(&g_arrive, 1u);
            if (my == NB - 1) {
                // Last arriver: all partials are globally visible (each block
                // fenced before arriving). Fixed-order pairwise total,
                // broadcast, then release.
                const float4* p4 = reinterpret_cast<const float4*>(g_part);
                float s = 0.f;
                #pragma unroll
                for (int i = 0; i < NB / 4; i++) {
                    float4 p = __ldcg(&p4[i]);        // fixed order i=0..7
                    s += (p.x + p.y) + (p.z + p.w);
                }
                g_total  = s;
                g_arrive = 0;                         // no concurrent arrivers left
                __threadfence();                      // total visible before release
                g_release = e0 + 1;                   // release everyone
            }
        }
    }

    // ---- overlap: softmax math while other blocks arrive ----
    const float rowmax = fmaxf(fmaxf(s_mx[4 * rg + 0], s_mx[4 * rg + 1]),
                               fmaxf(s_mx[4 * rg + 2], s_mx[4 * rg + 3]));
    float e = __expf(f.x - rowmax) + __expf(f.y - rowmax)
            + __expf(f.z - rowmax) + __expf(f.w - rowmax);
    #pragma unroll
    for (int o = 16; o > 0; o >>= 1)
        e += __shfl_xor_sync(0xffffffffu, e, o);
    if (lane == 0) s_e[warp] = e;

    // ---- t0: wait for release, grab broadcast total ----
    if (is_t0) {
        while (g_release == e0) { __nanosleep(32); }
        __threadfence();                              // acquire: order g_total read
        s_total = __ldcg(&g_total);
    }
    __syncthreads();   // BAR #2 (orders s_e and gates on release+total)

    const float lse = rowmax + __logf((s_e[4 * rg + 0] + s_e[4 * rg + 1])
                                    + (s_e[4 * rg + 2] + s_e[4 * rg + 3]));
    const float add = s_total - lse;

    // ---- epilogue straight from registers (feats never re-read) ----
    float4 o;
    o.x = f.x + add; o.y = f.y + add; o.z = f.z + add; o.w = f.w + add;
    reinterpret_cast<float4*>(out)[(size_t)b * (FEAT / 4) + l] = o;
}

extern "C" void kernel_launch(void* const* d_in, const int* in_sizes, int n_in,
                              void* d_out, int out_size)
{
    const float* feats   = (const float*)d_in[0];
    const float* centers = (const float*)d_in[1];
    const int*   labels  = (const int*)d_in[2];
    float* out = (float*)d_out;

    cl_fused_kernel<<<NB, NT>>>(feats, centers, labels, out);
}

// round 9
// speedup vs baseline: 1.0332x; 1.0332x over previous
#include <cuda_runtime.h>

#define BATCH 256
#define FEAT  512
#define NB1   32            // K1 blocks (power of 2 -> wrap-safe last-arriver test)
#define NT1   1024          // K1 threads/block: 32*1024 = 32768 float4s = whole field

// Scratch (allocation-free rule: __device__ globals). g_arrive is a monotone
// counter (mod-NB1 last-arriver test) -> replay-safe with no reset node.
__device__ __align__(16) float g_part[NB1];
__device__ float    g_total;
__device__ unsigned g_arrive = 0;

// ---------------------------------------------------------------------------
// K1: grand total of ||f_b - c_{y_b}||^2 over all rows. No per-row output.
// Fixed-shape reduction tree (thread-index keyed) -> bitwise deterministic.
// ---------------------------------------------------------------------------
__global__ void __launch_bounds__(NT1) cl_dist_kernel(
    const float* __restrict__ feats,
    const float* __restrict__ centers,
    const int*   __restrict__ labels)
{
    const int t    = threadIdx.x;
    const int warp = t >> 5;
    const int lane = t & 31;
    const int g    = blockIdx.x * NT1 + t;   // global float4 index [0, 32768)
    const int row  = g >> 7;                 // 128 float4s per row
    const int col  = g & 127;

    const long long lab = __ldg(&labels[row]);   // 128-thread broadcast per row

    float4 f = reinterpret_cast<const float4*>(feats)[g];
    float4 c = reinterpret_cast<const float4*>(centers)[lab * (FEAT / 4) + col];

    float d0 = f.x - c.x, d1 = f.y - c.y, d2 = f.z - c.z, d3 = f.w - c.w;
    float dist = d0 * d0 + d1 * d1 + d2 * d2 + d3 * d3;

    #pragma unroll
    for (int o = 16; o > 0; o >>= 1)
        dist += __shfl_xor_sync(0xffffffffu, dist, o);

    __shared__ float s_d[32];
    if (lane == 0) s_d[warp] = dist;
    __syncthreads();

    if (warp == 0) {
        float v = s_d[lane];
        #pragma unroll
        for (int o = 16; o > 0; o >>= 1)
            v += __shfl_xor_sync(0xffffffffu, v, o);
        if (lane == 0) {
            g_part[blockIdx.x] = v;
            __threadfence();                         // partial visible pre-arrive
            unsigned my = atomicAdd(&g_arrive, 1u);
            if ((my & (NB1 - 1)) == NB1 - 1) {       // last arriver this launch
                const float4* p4 = reinterpret_cast<const float4*>(g_part);
                float s = 0.f;
                #pragma unroll
                for (int i = 0; i < NB1 / 4; i++) {
                    float4 p = __ldcg(&p4[i]);       // fixed order
                    s += (p.x + p.y) + (p.z + p.w);
                }
                g_total = s;                         // flushed at kernel end
            }
        }
    }
}

// ---------------------------------------------------------------------------
// K2 (PDL secondary): per-row logsumexp computed locally; only g_total is
// consumed from K1, gated by cudaGridDependencySynchronize().
// ---------------------------------------------------------------------------
__global__ void __launch_bounds__(128) cl_out_kernel(
    const float* __restrict__ feats,
    float* __restrict__ out)
{
    const int b    = blockIdx.x;
    const int t    = threadIdx.x;
    const int warp = t >> 5;
    const int lane = t & 31;

    float4 f = reinterpret_cast<const float4*>(feats)[(size_t)b * (FEAT / 4) + t];

    float mx = fmaxf(fmaxf(f.x, f.y), fmaxf(f.z, f.w));
    #pragma unroll
    for (int o = 16; o > 0; o >>= 1)
        mx = fmaxf(mx, __shfl_xor_sync(0xffffffffu, mx, o));

    __shared__ float s_mx[4], s_e[4];
    if (lane == 0) s_mx[warp] = mx;
    __syncthreads();
    const float rowmax = fmaxf(fmaxf(s_mx[0], s_mx[1]), fmaxf(s_mx[2], s_mx[3]));

    float e = __expf(f.x - rowmax) + __expf(f.y - rowmax)
            + __expf(f.z - rowmax) + __expf(f.w - rowmax);
    #pragma unroll
    for (int o = 16; o > 0; o >>= 1)
        e += __shfl_xor_sync(0xffffffffu, e, o);
    if (lane == 0) s_e[warp] = e;
    __syncthreads();

    const float lse = rowmax + __logf((s_e[0] + s_e[1]) + (s_e[2] + s_e[3]));

    // Gate ONLY the g_total consumption on K1 completion (+ memory flush).
    cudaGridDependencySynchronize();
    const float total = __ldcg(&g_total);

    const float add = total - lse;
    float4 o;
    o.x = f.x + add; o.y = f.y + add; o.z = f.z + add; o.w = f.w + add;
    reinterpret_cast<float4*>(out)[(size_t)b * (FEAT / 4) + t] = o;
}

extern "C" void kernel_launch(void* const* d_in, const int* in_sizes, int n_in,
                              void* d_out, int out_size)
{
    const float* feats   = (const float*)d_in[0];
    const float* centers = (const float*)d_in[1];
    const int*   labels  = (const int*)d_in[2];
    float* out = (float*)d_out;

    cl_dist_kernel<<<NB1, NT1>>>(feats, centers, labels);

    // K2 with programmatic stream serialization: prologue overlaps K1.
    cudaLaunchConfig_t cfg = {};
    cfg.gridDim  = dim3(BATCH);
    cfg.blockDim = dim3(128);
    cfg.dynamicSmemBytes = 0;
    cfg.stream = 0;
    cudaLaunchAttribute attrs[1];
    attrs[0].id = cudaLaunchAttributeProgrammaticStreamSerialization;
    attrs[0].val.programmaticStreamSerializationAllowed = 1;
    cfg.attrs = attrs;
    cfg.numAttrs = 1;
    cudaLaunchKernelEx(&cfg, cl_out_kernel, feats, out);
}